// round 16
// baseline (speedup 1.0000x reference)
#include <cuda_runtime.h>
#include <math.h>
#include <stdint.h>

#define SEQ 50
#define DIM 32
#define NTHR 256
#define NWARP 8
#define FULLM 0xffffffffu
#define PITCH 36            // activation row pitch (floats); 144B: float4-aligned, frag-conflict-free
#define SROWS 164           // 150 rows + 14 pad (mt=3 over-read)

// Prep outputs (shared by all batches)
__device__ uint2  gWB[4 * 4 * 4 * 32];   // tf32 B fragments: [t][kk][nn][lane]; t=3 is raw Wo
__device__ float  gB2[96];               // folded bias (bias + b.W^T) for q,k,v
__device__ float  gSw[96];               // rowsum of g-scaled W for q,k,v

__device__ __forceinline__ uint32_t f2tf(float f) {
    uint32_t r;
    asm("cvt.rna.tf32.f32 %0, %1;" : "=r"(r) : "f"(f));
    return r;
}

__device__ __forceinline__ void mma_tf32(float c[4], const uint32_t a[4], uint2 b) {
    asm volatile(
        "mma.sync.aligned.m16n8k8.row.col.f32.tf32.tf32.f32 "
        "{%0,%1,%2,%3}, {%4,%5,%6,%7}, {%8,%9}, {%0,%1,%2,%3};"
        : "+f"(c[0]), "+f"(c[1]), "+f"(c[2]), "+f"(c[3])
        : "r"(a[0]), "r"(a[1]), "r"(a[2]), "r"(a[3]), "r"(b.x), "r"(b.y));
}

__global__ void prep_kernel(
    const float* __restrict__ ln_g, const float* __restrict__ ln_b,
    const float* __restrict__ Wq, const float* __restrict__ bq,
    const float* __restrict__ Wk, const float* __restrict__ bk,
    const float* __restrict__ Wv, const float* __restrict__ bv,
    const float* __restrict__ Wo)
{
    __shared__ float sWf[4 * 32 * 32];   // folded W' for q,k,v; raw Wo for t=3
    const int j = threadIdx.x;           // 128 threads
    if (j < 96) {
        int t = j >> 5, r = j & 31;
        const float* W    = (t == 0) ? Wq : (t == 1) ? Wk : Wv;
        const float* bias = (t == 0) ? bq : (t == 1) ? bk : bv;
        float b2 = bias[r], sw = 0.f;
        #pragma unroll
        for (int d = 0; d < DIM; d++) {
            float w  = W[r * DIM + d];
            float gw = w * ln_g[d];
            b2 = fmaf(w, ln_b[d], b2);
            sw += gw;
            sWf[(t * 32 + r) * 32 + d] = gw;
        }
        gB2[j] = b2;
        gSw[j] = sw;
    }
    for (int i = j; i < DIM * DIM; i += 128)
        sWf[3 * 1024 + i] = Wo[i];       // t=3: raw Wo, row-major [n][k]
    __syncthreads();
    // B fragments: B[k][n] = W'[n][k]; b0=(k=kk*8+l%4, n=nn*8+l/4), b1: k+4
    for (int idx = j; idx < 2048; idx += 128) {
        int l  = idx & 31;
        int nn = (idx >> 5) & 3;
        int kk = (idx >> 7) & 3;
        int t  = idx >> 9;
        int n  = nn * 8 + (l >> 2);
        int k0 = kk * 8 + (l & 3);
        float w0 = sWf[(t * 32 + n) * 32 + k0];
        float w1 = sWf[(t * 32 + n) * 32 + k0 + 4];
        gWB[idx] = make_uint2(f2tf(w0), f2tf(w1));
    }
}

__global__ __launch_bounds__(NTHR, 4) void mha_fused_kernel(
    const float* __restrict__ Q, const float* __restrict__ K, const float* __restrict__ V,
    const float* __restrict__ bo,
    float* __restrict__ out)
{
    __shared__ __align__(16) float sbuf[SROWS * PITCH];   // tf32 x -> projected in place; q->ctx(tf32)
    __shared__ uint2  sWB[2048];                          // tf32 B fragments (q,k,v,o)
    __shared__ __align__(8) float2 sStats[SROWS];         // (mu, inv)
    __shared__ __align__(8) float sB2[96], sSw[96];
    __shared__ __align__(8) float sboS[DIM];

    const int tid  = threadIdx.x;
    const int lane = tid & 31;
    const int wid  = tid >> 5;
    const size_t boff = (size_t)blockIdx.x * (SEQ * DIM);
    const float* Qb = Q + boff;
    const float* Kb = K + boff;
    const float* Vb = V + boff;

    // ---- stage weight fragments + params ----
    for (int i = tid; i < 2048; i += NTHR) sWB[i] = gWB[i];
    if (tid < 96) { sB2[tid] = gB2[tid]; sSw[tid] = gSw[tid]; }
    if (tid >= 96 && tid < 128) sboS[tid - 96] = bo[tid - 96];
    // zero the pad rows (150..163) so over-reads are finite
    for (int i = tid; i < (SROWS - 150) * PITCH; i += NTHR) sbuf[150 * PITCH + i] = 0.f;

    // ---- raw loads + LN stats (exact); store x truncated to tf32 ----
    {
        const int rsub = lane >> 3;
        const int rk   = lane & 7;
        for (int blk = wid; blk < 38; blk += NWARP) {
            int gr = blk * 4 + rsub;            // 0..151
            float4 xv = make_float4(0.f, 0.f, 0.f, 0.f);
            if (gr < 150) {
                int t = gr / SEQ;
                int r = gr - t * SEQ;
                const float* src = (t == 0) ? Qb : (t == 1) ? Kb : Vb;
                xv = *(const float4*)(src + r * DIM + rk * 4);
                uint4 tv = make_uint4(f2tf(xv.x), f2tf(xv.y), f2tf(xv.z), f2tf(xv.w));
                *(uint4*)(sbuf + gr * PITCH + rk * 4) = tv;
            }
            float s1 = xv.x + xv.y + xv.z + xv.w;
            float s2 = xv.x * xv.x + xv.y * xv.y + xv.z * xv.z + xv.w * xv.w;
            #pragma unroll
            for (int o = 4; o; o >>= 1) {
                s1 += __shfl_xor_sync(FULLM, s1, o);
                s2 += __shfl_xor_sync(FULLM, s2, o);
            }
            if (rk == 0 && gr < 150) {
                float mu  = s1 * (1.0f / DIM);
                float var = s2 * (1.0f / DIM) - mu * mu;
                sStats[gr] = make_float2(mu, rsqrtf(var + 1e-5f));
            }
        }
    }
    __syncthreads();

    // ---- QKV projections via tf32 MMA: 12 FULL tasks = t(3) x mt(4), 16x32x32 per warp.
    // Race-free: each task writes only the rows it owns; over-read rows feed discarded lanes.
    for (int task = wid; task < 12; task += NWARP) {
        const int t  = task >> 2;
        const int mt = task & 3;
        const int gr0 = t * 50 + mt * 16;
        const int r0  = gr0 + (lane >> 2);
        const int c4  = lane & 3;

        uint32_t a[4][4];
        const int base0 = r0 * PITCH + c4;
        const int base1 = base0 + 8 * PITCH;
        #pragma unroll
        for (int kk = 0; kk < 4; kk++) {
            a[kk][0] = __float_as_uint(sbuf[base0 + kk * 8]);
            a[kk][1] = __float_as_uint(sbuf[base1 + kk * 8]);
            a[kk][2] = __float_as_uint(sbuf[base0 + kk * 8 + 4]);
            a[kk][3] = __float_as_uint(sbuf[base1 + kk * 8 + 4]);
        }
        float c[4][4];
        #pragma unroll
        for (int nn = 0; nn < 4; nn++)
            #pragma unroll
            for (int q = 0; q < 4; q++) c[nn][q] = 0.f;

        const int wb = t * 512 + lane;
        #pragma unroll
        for (int nn = 0; nn < 4; nn++) {
            #pragma unroll
            for (int kk = 0; kk < 4; kk++)
                mma_tf32(c[nn], a[kk], sWB[wb + (kk * 4 + nn) * 32]);
        }

        // epilogue: LN affine + predicated store (fp32)
        const float2 st0 = sStats[r0];
        const float2 st1 = sStats[r0 + 8];
        const bool v0 = (mt * 16 + (lane >> 2)) < 50;
        const bool v1 = (mt * 16 + (lane >> 2) + 8) < 50;
        #pragma unroll
        for (int nn = 0; nn < 4; nn++) {
            const int col = nn * 8 + 2 * c4;
            float2 bb = *(const float2*)&sB2[t * 32 + col];
            float2 ss = *(const float2*)&sSw[t * 32 + col];
            float o00 = fmaf(st0.y, fmaf(-st0.x, ss.x, c[nn][0]), bb.x);
            float o01 = fmaf(st0.y, fmaf(-st0.x, ss.y, c[nn][1]), bb.y);
            float o10 = fmaf(st1.y, fmaf(-st1.x, ss.x, c[nn][2]), bb.x);
            float o11 = fmaf(st1.y, fmaf(-st1.x, ss.y, c[nn][3]), bb.y);
            if (v0) *(float2*)&sbuf[r0 * PITCH + col]       = make_float2(o00, o01);
            if (v1) *(float2*)&sbuf[(r0 + 8) * PITCH + col] = make_float2(o10, o11);
        }
    }
    __syncthreads();

    // ---- paired causal attention (scalar): thread = (head, pair p); ctx stored as tf32 ----
    if (tid < 4 * (SEQ / 2)) {
        const int h = tid & 3;
        const int p = tid >> 2;           // 0..24
        const int i2 = SEQ - 1 - p;       // 25..49
        const float* sk_ = sbuf + SEQ * PITCH;
        const float* sv_ = sbuf + 2 * SEQ * PITCH;
        const float scale = 0.35355339059327373f;  // 1/sqrt(8)

        const float* q1p = sbuf + p  * PITCH + h * 8;
        const float* q2p = sbuf + i2 * PITCH + h * 8;
        float4 q1a = *(const float4*)q1p, q1b = *(const float4*)(q1p + 4);
        float4 q2a = *(const float4*)q2p, q2b = *(const float4*)(q2p + 4);
        q1a.x *= scale; q1a.y *= scale; q1a.z *= scale; q1a.w *= scale;
        q1b.x *= scale; q1b.y *= scale; q1b.z *= scale; q1b.w *= scale;
        q2a.x *= scale; q2a.y *= scale; q2a.z *= scale; q2a.w *= scale;
        q2b.x *= scale; q2b.y *= scale; q2b.z *= scale; q2b.w *= scale;

        float ssum1 = 0.f, ssum2 = 0.f;
        float4 a1a = make_float4(0.f,0.f,0.f,0.f), a1b = make_float4(0.f,0.f,0.f,0.f);
        float4 a2a = make_float4(0.f,0.f,0.f,0.f), a2b = make_float4(0.f,0.f,0.f,0.f);

        for (int j = 0; j <= i2; j++) {
            const float* kr = sk_ + j * PITCH + h * 8;
            float4 k0 = *(const float4*)kr;
            float4 k1 = *(const float4*)(kr + 4);
            const float* vr = sv_ + j * PITCH + h * 8;
            float4 v0 = *(const float4*)vr;
            float4 v1 = *(const float4*)(vr + 4);

            float d2 = q2a.x*k0.x + q2a.y*k0.y + q2a.z*k0.z + q2a.w*k0.w
                     + q2b.x*k1.x + q2b.y*k1.y + q2b.z*k1.z + q2b.w*k1.w;
            float w2 = __expf(d2);
            ssum2 += w2;
            a2a.x = fmaf(w2, v0.x, a2a.x); a2a.y = fmaf(w2, v0.y, a2a.y);
            a2a.z = fmaf(w2, v0.z, a2a.z); a2a.w = fmaf(w2, v0.w, a2a.w);
            a2b.x = fmaf(w2, v1.x, a2b.x); a2b.y = fmaf(w2, v1.y, a2b.y);
            a2b.z = fmaf(w2, v1.z, a2b.z); a2b.w = fmaf(w2, v1.w, a2b.w);

            if (j <= p) {
                float d1 = q1a.x*k0.x + q1a.y*k0.y + q1a.z*k0.z + q1a.w*k0.w
                         + q1b.x*k1.x + q1b.y*k1.y + q1b.z*k1.z + q1b.w*k1.w;
                float w1 = __expf(d1);
                ssum1 += w1;
                a1a.x = fmaf(w1, v0.x, a1a.x); a1a.y = fmaf(w1, v0.y, a1a.y);
                a1a.z = fmaf(w1, v0.z, a1a.z); a1a.w = fmaf(w1, v0.w, a1a.w);
                a1b.x = fmaf(w1, v1.x, a1b.x); a1b.y = fmaf(w1, v1.y, a1b.y);
                a1b.z = fmaf(w1, v1.z, a1b.z); a1b.w = fmaf(w1, v1.w, a1b.w);
            }
        }
        float inv1 = 1.0f / ssum1;
        float inv2 = 1.0f / ssum2;
        uint32_t* c1 = (uint32_t*)(sbuf + p  * PITCH + h * 8);
        uint32_t* c2 = (uint32_t*)(sbuf + i2 * PITCH + h * 8);
        // store ctx rounded to tf32 (A operand of the O-GEMM)
        c1[0] = f2tf(a1a.x * inv1); c1[1] = f2tf(a1a.y * inv1);
        c1[2] = f2tf(a1a.z * inv1); c1[3] = f2tf(a1a.w * inv1);
        c1[4] = f2tf(a1b.x * inv1); c1[5] = f2tf(a1b.y * inv1);
        c1[6] = f2tf(a1b.z * inv1); c1[7] = f2tf(a1b.w * inv1);
        c2[0] = f2tf(a2a.x * inv2); c2[1] = f2tf(a2a.y * inv2);
        c2[2] = f2tf(a2a.z * inv2); c2[3] = f2tf(a2a.w * inv2);
        c2[4] = f2tf(a2b.x * inv2); c2[5] = f2tf(a2b.y * inv2);
        c2[6] = f2tf(a2b.z * inv2); c2[7] = f2tf(a2b.w * inv2);
    }
    __syncthreads();

    // ---- output projection via tf32 MMA: 8 half-tasks = mt(4) x nh(2); + bias + residual.
    // Writes go to GMEM only -> no smem race.
    {
        const int mt = wid >> 1;
        const int nh = wid & 1;
        const int c4 = lane & 3;
        const int r0 = mt * 16 + (lane >> 2);     // ctx rows live at sbuf rows 0..49

        uint32_t a[4][4];
        const int base0 = r0 * PITCH + c4;
        const int base1 = base0 + 8 * PITCH;
        #pragma unroll
        for (int kk = 0; kk < 4; kk++) {
            a[kk][0] = __float_as_uint(sbuf[base0 + kk * 8]);
            a[kk][1] = __float_as_uint(sbuf[base1 + kk * 8]);
            a[kk][2] = __float_as_uint(sbuf[base0 + kk * 8 + 4]);
            a[kk][3] = __float_as_uint(sbuf[base1 + kk * 8 + 4]);
        }
        float c[2][4];
        #pragma unroll
        for (int nn = 0; nn < 2; nn++)
            #pragma unroll
            for (int q = 0; q < 4; q++) c[nn][q] = 0.f;

        const int wb = 3 * 512 + lane;
        #pragma unroll
        for (int nn2 = 0; nn2 < 2; nn2++) {
            const int nn = nh * 2 + nn2;
            #pragma unroll
            for (int kk = 0; kk < 4; kk++)
                mma_tf32(c[nn2], a[kk], sWB[wb + (kk * 4 + nn) * 32]);
        }

        const int row0 = mt * 16 + (lane >> 2);
        const int row1 = row0 + 8;
        const bool v0 = row0 < 50;
        const bool v1 = row1 < 50;
        float* ob = out + boff;
        #pragma unroll
        for (int nn2 = 0; nn2 < 2; nn2++) {
            const int col = (nh * 2 + nn2) * 8 + 2 * c4;
            float2 bb = *(const float2*)&sboS[col];
            if (v0) {
                float2 rs = __ldg((const float2*)(Qb + row0 * DIM + col));
                *(float2*)(ob + row0 * DIM + col) =
                    make_float2(c[nn2][0] + bb.x + rs.x, c[nn2][1] + bb.y + rs.y);
            }
            if (v1) {
                float2 rs = __ldg((const float2*)(Qb + row1 * DIM + col));
                *(float2*)(ob + row1 * DIM + col) =
                    make_float2(c[nn2][2] + bb.x + rs.x, c[nn2][3] + bb.y + rs.y);
            }
        }
    }
}

extern "C" void kernel_launch(void* const* d_in, const int* in_sizes, int n_in,
                              void* d_out, int out_size) {
    const float* Q    = (const float*)d_in[0];
    const float* K    = (const float*)d_in[1];
    const float* V    = (const float*)d_in[2];
    // d_in[3] = mask (static causal triu, implemented analytically)
    const float* ln_g = (const float*)d_in[4];
    const float* ln_b = (const float*)d_in[5];
    const float* Wq   = (const float*)d_in[6];
    const float* bq   = (const float*)d_in[7];
    const float* Wk   = (const float*)d_in[8];
    const float* bk   = (const float*)d_in[9];
    const float* Wv   = (const float*)d_in[10];
    const float* bv   = (const float*)d_in[11];
    const float* Wo   = (const float*)d_in[12];
    const float* bo   = (const float*)d_in[13];
    float* out = (float*)d_out;

    const int B = in_sizes[0] / (SEQ * DIM);  // 16384
    prep_kernel<<<1, 128>>>(ln_g, ln_b, Wq, bq, Wk, bk, Wv, bv, Wo);
    mha_fused_kernel<<<B, NTHR>>>(Q, K, V, bo, out);
}

// round 17
// speedup vs baseline: 1.4360x; 1.4360x over previous
#include <cuda_runtime.h>
#include <math.h>
#include <stdint.h>

#define SEQ 50
#define DIM 32
#define NTHR 256
#define NWARP 8
#define FULLM 0xffffffffu
#define PITCH 36            // activation row pitch (floats); 144B: float4-aligned, frag-conflict-free
#define SROWS 164           // 150 rows + 14 pad (mt=3 over-read)

// Prep outputs (shared by all batches)
__device__ uint2  gWB[4 * 4 * 4 * 32];   // tf32 B fragments: [t][kk][nn][lane]; t=3 is raw Wo
__device__ float  gB2[96];               // folded bias (bias + b.W^T) for q,k,v
__device__ float  gSw[96];               // rowsum of g-scaled W for q,k,v

__device__ __forceinline__ uint32_t f2tf(float f) {
    uint32_t r;
    asm("cvt.rna.tf32.f32 %0, %1;" : "=r"(r) : "f"(f));
    return r;
}

__device__ __forceinline__ void mma_tf32(float c[4], const uint32_t a[4], uint2 b) {
    asm volatile(
        "mma.sync.aligned.m16n8k8.row.col.f32.tf32.tf32.f32 "
        "{%0,%1,%2,%3}, {%4,%5,%6,%7}, {%8,%9}, {%0,%1,%2,%3};"
        : "+f"(c[0]), "+f"(c[1]), "+f"(c[2]), "+f"(c[3])
        : "r"(a[0]), "r"(a[1]), "r"(a[2]), "r"(a[3]), "r"(b.x), "r"(b.y));
}

__global__ void prep_kernel(
    const float* __restrict__ ln_g, const float* __restrict__ ln_b,
    const float* __restrict__ Wq, const float* __restrict__ bq,
    const float* __restrict__ Wk, const float* __restrict__ bk,
    const float* __restrict__ Wv, const float* __restrict__ bv,
    const float* __restrict__ Wo)
{
    __shared__ float sWf[4 * 32 * 32];   // folded W' for q,k,v; raw Wo for t=3
    const int j = threadIdx.x;           // 128 threads
    if (j < 96) {
        int t = j >> 5, r = j & 31;
        const float* W    = (t == 0) ? Wq : (t == 1) ? Wk : Wv;
        const float* bias = (t == 0) ? bq : (t == 1) ? bk : bv;
        float b2 = bias[r], sw = 0.f;
        #pragma unroll
        for (int d = 0; d < DIM; d++) {
            float w  = W[r * DIM + d];
            float gw = w * ln_g[d];
            b2 = fmaf(w, ln_b[d], b2);
            sw += gw;
            sWf[(t * 32 + r) * 32 + d] = gw;
        }
        gB2[j] = b2;
        gSw[j] = sw;
    }
    for (int i = j; i < DIM * DIM; i += 128)
        sWf[3 * 1024 + i] = Wo[i];       // t=3: raw Wo, row-major [n][k]
    __syncthreads();
    // B fragments: B[k][n] = W'[n][k]; b0=(k=kk*8+l%4, n=nn*8+l/4), b1: k+4
    for (int idx = j; idx < 2048; idx += 128) {
        int l  = idx & 31;
        int nn = (idx >> 5) & 3;
        int kk = (idx >> 7) & 3;
        int t  = idx >> 9;
        int n  = nn * 8 + (l >> 2);
        int k0 = kk * 8 + (l & 3);
        float w0 = sWf[(t * 32 + n) * 32 + k0];
        float w1 = sWf[(t * 32 + n) * 32 + k0 + 4];
        gWB[idx] = make_uint2(f2tf(w0), f2tf(w1));
    }
}

__global__ __launch_bounds__(NTHR, 4) void mha_fused_kernel(
    const float* __restrict__ Q, const float* __restrict__ K, const float* __restrict__ V,
    const float* __restrict__ bo,
    float* __restrict__ out)
{
    __shared__ __align__(16) float sbuf[SROWS * PITCH];   // tf32 x -> projected in place; q->ctx(tf32)
    __shared__ uint2  sWB[2048];                          // tf32 B fragments (q,k,v,o)
    __shared__ __align__(8) float2 sStats[SROWS];         // (mu, inv)
    __shared__ __align__(8) float sB2[96], sSw[96];
    __shared__ __align__(8) float sboS[DIM];

    const int tid  = threadIdx.x;
    const int lane = tid & 31;
    const int wid  = tid >> 5;
    const size_t boff = (size_t)blockIdx.x * (SEQ * DIM);
    const float* Qb = Q + boff;
    const float* Kb = K + boff;
    const float* Vb = V + boff;

    // ---- stage weight fragments + params ----
    for (int i = tid; i < 2048; i += NTHR) sWB[i] = gWB[i];
    if (tid < 96) { sB2[tid] = gB2[tid]; sSw[tid] = gSw[tid]; }
    if (tid >= 96 && tid < 128) sboS[tid - 96] = bo[tid - 96];
    // zero the pad rows (150..163) so over-reads are finite
    for (int i = tid; i < (SROWS - 150) * PITCH; i += NTHR) sbuf[150 * PITCH + i] = 0.f;

    // ---- raw loads + LN stats (exact); store x truncated to tf32 ----
    {
        const int rsub = lane >> 3;
        const int rk   = lane & 7;
        for (int blk = wid; blk < 38; blk += NWARP) {
            int gr = blk * 4 + rsub;            // 0..151
            float4 xv = make_float4(0.f, 0.f, 0.f, 0.f);
            if (gr < 150) {
                int t = gr / SEQ;
                int r = gr - t * SEQ;
                const float* src = (t == 0) ? Qb : (t == 1) ? Kb : Vb;
                xv = *(const float4*)(src + r * DIM + rk * 4);
                uint4 tv = make_uint4(f2tf(xv.x), f2tf(xv.y), f2tf(xv.z), f2tf(xv.w));
                *(uint4*)(sbuf + gr * PITCH + rk * 4) = tv;
            }
            float s1 = xv.x + xv.y + xv.z + xv.w;
            float s2 = xv.x * xv.x + xv.y * xv.y + xv.z * xv.z + xv.w * xv.w;
            #pragma unroll
            for (int o = 4; o; o >>= 1) {
                s1 += __shfl_xor_sync(FULLM, s1, o);
                s2 += __shfl_xor_sync(FULLM, s2, o);
            }
            if (rk == 0 && gr < 150) {
                float mu  = s1 * (1.0f / DIM);
                float var = s2 * (1.0f / DIM) - mu * mu;
                sStats[gr] = make_float2(mu, rsqrtf(var + 1e-5f));
            }
        }
    }
    __syncthreads();

    // ---- QKV projections via tf32 MMA: 12 FULL tasks = t(3) x mt(4), 16x32x32 per warp.
    // Race-free: each task writes only the rows it owns; over-read rows feed discarded lanes.
    for (int task = wid; task < 12; task += NWARP) {
        const int t  = task >> 2;
        const int mt = task & 3;
        const int gr0 = t * 50 + mt * 16;
        const int r0  = gr0 + (lane >> 2);
        const int c4  = lane & 3;

        uint32_t a[4][4];
        const int base0 = r0 * PITCH + c4;
        const int base1 = base0 + 8 * PITCH;
        #pragma unroll
        for (int kk = 0; kk < 4; kk++) {
            a[kk][0] = __float_as_uint(sbuf[base0 + kk * 8]);
            a[kk][1] = __float_as_uint(sbuf[base1 + kk * 8]);
            a[kk][2] = __float_as_uint(sbuf[base0 + kk * 8 + 4]);
            a[kk][3] = __float_as_uint(sbuf[base1 + kk * 8 + 4]);
        }
        float c[4][4];
        #pragma unroll
        for (int nn = 0; nn < 4; nn++)
            #pragma unroll
            for (int q = 0; q < 4; q++) c[nn][q] = 0.f;

        const int wb = t * 512 + lane;
        #pragma unroll
        for (int nn = 0; nn < 4; nn++) {
            #pragma unroll
            for (int kk = 0; kk < 4; kk++)
                mma_tf32(c[nn], a[kk], sWB[wb + (kk * 4 + nn) * 32]);
        }

        // epilogue: LN affine + predicated store (fp32)
        const float2 st0 = sStats[r0];
        const float2 st1 = sStats[r0 + 8];
        const bool v0 = (mt * 16 + (lane >> 2)) < 50;
        const bool v1 = (mt * 16 + (lane >> 2) + 8) < 50;
        #pragma unroll
        for (int nn = 0; nn < 4; nn++) {
            const int col = nn * 8 + 2 * c4;
            float2 bb = *(const float2*)&sB2[t * 32 + col];
            float2 ss = *(const float2*)&sSw[t * 32 + col];
            float o00 = fmaf(st0.y, fmaf(-st0.x, ss.x, c[nn][0]), bb.x);
            float o01 = fmaf(st0.y, fmaf(-st0.x, ss.y, c[nn][1]), bb.y);
            float o10 = fmaf(st1.y, fmaf(-st1.x, ss.x, c[nn][2]), bb.x);
            float o11 = fmaf(st1.y, fmaf(-st1.x, ss.y, c[nn][3]), bb.y);
            if (v0) *(float2*)&sbuf[r0 * PITCH + col]       = make_float2(o00, o01);
            if (v1) *(float2*)&sbuf[(r0 + 8) * PITCH + col] = make_float2(o10, o11);
        }
    }
    __syncthreads();

    // ---- paired causal attention (scalar): thread = (head, pair p); ctx stored tf32, packed ----
    if (tid < 4 * (SEQ / 2)) {
        const int h = tid & 3;
        const int p = tid >> 2;           // 0..24
        const int i2 = SEQ - 1 - p;       // 25..49
        const float* sk_ = sbuf + SEQ * PITCH;
        const float* sv_ = sbuf + 2 * SEQ * PITCH;
        const float scale = 0.35355339059327373f;  // 1/sqrt(8)

        const float* q1p = sbuf + p  * PITCH + h * 8;
        const float* q2p = sbuf + i2 * PITCH + h * 8;
        float4 q1a = *(const float4*)q1p, q1b = *(const float4*)(q1p + 4);
        float4 q2a = *(const float4*)q2p, q2b = *(const float4*)(q2p + 4);
        q1a.x *= scale; q1a.y *= scale; q1a.z *= scale; q1a.w *= scale;
        q1b.x *= scale; q1b.y *= scale; q1b.z *= scale; q1b.w *= scale;
        q2a.x *= scale; q2a.y *= scale; q2a.z *= scale; q2a.w *= scale;
        q2b.x *= scale; q2b.y *= scale; q2b.z *= scale; q2b.w *= scale;

        float ssum1 = 0.f, ssum2 = 0.f;
        float4 a1a = make_float4(0.f,0.f,0.f,0.f), a1b = make_float4(0.f,0.f,0.f,0.f);
        float4 a2a = make_float4(0.f,0.f,0.f,0.f), a2b = make_float4(0.f,0.f,0.f,0.f);

        for (int j = 0; j <= i2; j++) {
            const float* kr = sk_ + j * PITCH + h * 8;
            float4 k0 = *(const float4*)kr;
            float4 k1 = *(const float4*)(kr + 4);
            const float* vr = sv_ + j * PITCH + h * 8;
            float4 v0 = *(const float4*)vr;
            float4 v1 = *(const float4*)(vr + 4);

            float d2 = q2a.x*k0.x + q2a.y*k0.y + q2a.z*k0.z + q2a.w*k0.w
                     + q2b.x*k1.x + q2b.y*k1.y + q2b.z*k1.z + q2b.w*k1.w;
            float w2 = __expf(d2);
            ssum2 += w2;
            a2a.x = fmaf(w2, v0.x, a2a.x); a2a.y = fmaf(w2, v0.y, a2a.y);
            a2a.z = fmaf(w2, v0.z, a2a.z); a2a.w = fmaf(w2, v0.w, a2a.w);
            a2b.x = fmaf(w2, v1.x, a2b.x); a2b.y = fmaf(w2, v1.y, a2b.y);
            a2b.z = fmaf(w2, v1.z, a2b.z); a2b.w = fmaf(w2, v1.w, a2b.w);

            if (j <= p) {
                float d1 = q1a.x*k0.x + q1a.y*k0.y + q1a.z*k0.z + q1a.w*k0.w
                         + q1b.x*k1.x + q1b.y*k1.y + q1b.z*k1.z + q1b.w*k1.w;
                float w1 = __expf(d1);
                ssum1 += w1;
                a1a.x = fmaf(w1, v0.x, a1a.x); a1a.y = fmaf(w1, v0.y, a1a.y);
                a1a.z = fmaf(w1, v0.z, a1a.z); a1a.w = fmaf(w1, v0.w, a1a.w);
                a1b.x = fmaf(w1, v1.x, a1b.x); a1b.y = fmaf(w1, v1.y, a1b.y);
                a1b.z = fmaf(w1, v1.z, a1b.z); a1b.w = fmaf(w1, v1.w, a1b.w);
            }
        }
        float inv1 = 1.0f / ssum1;
        float inv2 = 1.0f / ssum2;
        // packed tf32 ctx stores: 2x STS.128 per query row
        uint4 p1a = make_uint4(f2tf(a1a.x*inv1), f2tf(a1a.y*inv1), f2tf(a1a.z*inv1), f2tf(a1a.w*inv1));
        uint4 p1b = make_uint4(f2tf(a1b.x*inv1), f2tf(a1b.y*inv1), f2tf(a1b.z*inv1), f2tf(a1b.w*inv1));
        uint4 p2a = make_uint4(f2tf(a2a.x*inv2), f2tf(a2a.y*inv2), f2tf(a2a.z*inv2), f2tf(a2a.w*inv2));
        uint4 p2b = make_uint4(f2tf(a2b.x*inv2), f2tf(a2b.y*inv2), f2tf(a2b.z*inv2), f2tf(a2b.w*inv2));
        uint4* c1 = (uint4*)(sbuf + p  * PITCH + h * 8);
        uint4* c2 = (uint4*)(sbuf + i2 * PITCH + h * 8);
        c1[0] = p1a; c1[1] = p1b;
        c2[0] = p2a; c2[1] = p2b;
    }
    __syncthreads();

    // ---- output projection via tf32 MMA: 8 half-tasks = mt(4) x nh(2).
    // Results staged into free smem rows 50..99 (K rows are dead); coalesced epilogue after sync.
    {
        const int mt = wid >> 1;
        const int nh = wid & 1;
        const int c4 = lane & 3;
        const int r0 = mt * 16 + (lane >> 2);     // ctx rows live at sbuf rows 0..49

        uint32_t a[4][4];
        const int base0 = r0 * PITCH + c4;
        const int base1 = base0 + 8 * PITCH;
        #pragma unroll
        for (int kk = 0; kk < 4; kk++) {
            a[kk][0] = __float_as_uint(sbuf[base0 + kk * 8]);
            a[kk][1] = __float_as_uint(sbuf[base1 + kk * 8]);
            a[kk][2] = __float_as_uint(sbuf[base0 + kk * 8 + 4]);
            a[kk][3] = __float_as_uint(sbuf[base1 + kk * 8 + 4]);
        }
        float c[2][4];
        #pragma unroll
        for (int nn = 0; nn < 2; nn++)
            #pragma unroll
            for (int q = 0; q < 4; q++) c[nn][q] = 0.f;

        const int wb = 3 * 512 + lane;
        #pragma unroll
        for (int nn2 = 0; nn2 < 2; nn2++) {
            const int nn = nh * 2 + nn2;
            #pragma unroll
            for (int kk = 0; kk < 4; kk++)
                mma_tf32(c[nn2], a[kk], sWB[wb + (kk * 4 + nn) * 32]);
        }

        const int row0 = mt * 16 + (lane >> 2);
        const int row1 = row0 + 8;
        const bool v0 = row0 < 50;
        const bool v1 = row1 < 50;
        #pragma unroll
        for (int nn2 = 0; nn2 < 2; nn2++) {
            const int col = (nh * 2 + nn2) * 8 + 2 * c4;
            if (v0) *(float2*)&sbuf[(50 + row0) * PITCH + col] = make_float2(c[nn2][0], c[nn2][1]);
            if (v1) *(float2*)&sbuf[(50 + row1) * PITCH + col] = make_float2(c[nn2][2], c[nn2][3]);
        }
    }
    __syncthreads();

    // ---- coalesced final epilogue: + bias + residual, gmem pattern identical to scalar R13 ----
    {
        const float b2 = sboS[lane];
        float* ob = out + boff;
        const int r0 = (wid * SEQ) >> 3;
        const int r1 = ((wid + 1) * SEQ) >> 3;
        for (int r = r0; r < r1; r++) {
            float dot = sbuf[(50 + r) * PITCH + lane];
            ob[r * DIM + lane] = dot + b2 + Qb[r * DIM + lane];
        }
    }
}

extern "C" void kernel_launch(void* const* d_in, const int* in_sizes, int n_in,
                              void* d_out, int out_size) {
    const float* Q    = (const float*)d_in[0];
    const float* K    = (const float*)d_in[1];
    const float* V    = (const float*)d_in[2];
    // d_in[3] = mask (static causal triu, implemented analytically)
    const float* ln_g = (const float*)d_in[4];
    const float* ln_b = (const float*)d_in[5];
    const float* Wq   = (const float*)d_in[6];
    const float* bq   = (const float*)d_in[7];
    const float* Wk   = (const float*)d_in[8];
    const float* bk   = (const float*)d_in[9];
    const float* Wv   = (const float*)d_in[10];
    const float* bv   = (const float*)d_in[11];
    const float* Wo   = (const float*)d_in[12];
    const float* bo   = (const float*)d_in[13];
    float* out = (float*)d_out;

    const int B = in_sizes[0] / (SEQ * DIM);  // 16384
    prep_kernel<<<1, 128>>>(ln_g, ln_b, Wq, bq, Wk, bk, Wv, bv, Wo);
    mha_fused_kernel<<<B, NTHR>>>(Q, K, V, bo, out);
}